// round 10
// baseline (speedup 1.0000x reference)
#include <cuda_runtime.h>

#define DD       512
#define TSEQ     512
#define NTOK     1024         // B*T
#define NTHR     128          // threads per block (4 warps)
#define TPB      4            // tokens per block
#define NBLK     (NTOK/TPB)   // 256 blocks (2/SM by smem -> all co-resident)
#define WE_STR   26           // padded W_enc row stride in floats (even: LDS.64 aligned)

// Dynamic smem layout: [ W_enc padded 512*26 | W_dec 24*512 ] floats
#define SMEM_WE_FLOATS  (DD * WE_STR)        // 13312
#define SMEM_WD_FLOATS  (24 * DD)            // 12288
#define SMEM_DYN_BYTES  ((SMEM_WE_FLOATS + SMEM_WD_FLOATS) * 4)   // 102400

__device__ float        g_partial[NTOK];
__device__ float        g_fac;
__device__ unsigned int g_cnt;    // arrival counter (self-resetting)
__device__ unsigned int g_cnt2;   // departure counter (self-resetting)
__device__ unsigned int g_flag;   // release flag     (self-resetting)

__device__ __forceinline__ float warpSum(float v) {
#pragma unroll
    for (int o = 16; o > 0; o >>= 1) v += __shfl_xor_sync(0xffffffffu, v, o);
    return v;  // butterfly: same value in all lanes, deterministic
}

// Deterministic block-wide sum (4 warps), broadcast to all threads.
__device__ __forceinline__ float blockSum(float v, float* red) {
    __syncthreads();                       // protect red[] reuse
    int lane = threadIdx.x & 31, w = threadIdx.x >> 5;
    v = warpSum(v);
    if (lane == 0) red[w] = v;
    __syncthreads();
    return red[0] + red[1] + red[2] + red[3];   // fixed order, all threads
}

__global__ __launch_bounds__(NTHR, 2) void fused_kernel(
    const int*   __restrict__ token_ids,
    const float* __restrict__ resonances,
    const float* __restrict__ emb_scales,
    const float* __restrict__ emb_shifts,
    const float* __restrict__ emb_norm,
    const float* __restrict__ frac_norm,
    const float* __restrict__ W_enc,   // [D,24]
    const float* __restrict__ b_enc,   // [24]
    const float* __restrict__ W_dec,   // [24,D]
    const float* __restrict__ b_dec,   // [D]
    const float* __restrict__ ecc_p,
    const float* __restrict__ ep_p,
    float*       __restrict__ out)     // [B,T,D]
{
    extern __shared__ float smem_dyn[];
    float* wenc_s = smem_dyn;                     // [512][26] padded
    float* wdec_s = smem_dyn + SMEM_WE_FLOATS;    // [24][512]

    __shared__ float red[4];
    __shared__ float e0s[DD];
    __shared__ float proj_s[24];
    __shared__ float latt_s[12];
    __shared__ float corr_s[24];
    __shared__ float ein2_s;
    __shared__ float fac_s;
    __shared__ int   done_s;

    const int tid  = threadIdx.x;
    const int lane = tid & 31;
    const int w    = tid >> 5;
    const int bid  = blockIdx.x;

    // ---- stage weights into smem (once per block, coalesced float4) ----
#pragma unroll
    for (int i4 = tid; i4 < (24 * DD) / 4; i4 += NTHR) {
        // W_dec: verbatim copy
        ((float4*)wdec_s)[i4] = ((const float4*)W_dec)[i4];
        // W_enc: repack rows of 24 -> stride 26 (consecutive STS banks, ~no conflict)
        float4 v = ((const float4*)W_enc)[i4];
        int e = i4 * 4;
        float vv[4] = {v.x, v.y, v.z, v.w};
#pragma unroll
        for (int k = 0; k < 4; k++) {
            int ee = e + k;
            wenc_s[(ee / 24) * WE_STR + (ee % 24)] = vv[k];
        }
    }

    // ---- per-block invariants (shared by all 4 tokens) ----
    const float4 rs4 = ((const float4*)resonances)[tid];
    const float4 sc4 = ((const float4*)emb_scales)[tid];
    const float4 sh4 = ((const float4*)emb_shifts)[tid];
    const float4 bd4 = ((const float4*)b_dec)[tid];
    const float rsv[4] = {rs4.x, rs4.y, rs4.z, rs4.w};
    const float scv[4] = {sc4.x, sc4.y, sc4.z, sc4.w};
    const float shv[4] = {sh4.x, sh4.y, sh4.z, sh4.w};
    const float embn = emb_norm[0];
    const float eccv = ecc_p[0];
    const float epv  = ep_p[0];
    __syncthreads();   // weights staged

    float4 rr[TPB];
    float  fpre[TPB];
    float  part[TPB];

#pragma unroll 1
    for (int it = 0; it < TPB; it++) {
        const int tg = bid * TPB + it;
        const int t  = tg & (TSEQ - 1);
        const float tv   = (float)(token_ids[tg] % 1000000) / 1000000.0f;
        const float base = tv + (float)t;

        // ---- embedding: comp = cos*(1+sin)+sin^2, scale/shift; d = 4*tid+i ----
        float e0[4];
        float ss = 0.0f;
#pragma unroll
        for (int i = 0; i < 4; i++) {
            float s, c;
            sincosf(rsv[i] * base, &s, &c);
            float v = (c * (1.0f + s) + s * s) * scv[i] + shv[i];
            e0[i] = v;
            ss += v * v;
        }
        float tn = sqrtf(blockSum(ss, red));
        // After normalize, ||emb|| == embn up to ~1e-7 rounding; skip 2nd reduce.
        float e_in = (tn > 0.0f) ? embn : 0.0f;

        float4 ev4;
#pragma unroll
        for (int i = 0; i < 4; i++) {
            float v = (tn > 0.0f) ? (e0[i] * embn) / tn : e0[i];
            ((float*)&ev4)[i] = v;
        }
        ((float4*)e0s)[tid] = ev4;
        __syncthreads();

        // ---- proj = emb @ W_enc + b_enc: warp w owns outputs [6w,6w+6) ----
        {
            const int lbase = w * 6;
            float acc0=0.f, acc1=0.f, acc2=0.f, acc3=0.f, acc4=0.f, acc5=0.f;
#pragma unroll
            for (int j = 0; j < 16; j++) {
                int d = lane + 32 * j;
                float ev = e0s[d];
                const float2* w2 = (const float2*)(wenc_s + d * WE_STR + lbase);
                float2 a = w2[0], b = w2[1], c = w2[2];
                acc0 += ev * a.x;  acc1 += ev * a.y;
                acc2 += ev * b.x;  acc3 += ev * b.y;
                acc4 += ev * c.x;  acc5 += ev * c.y;
            }
            acc0 = warpSum(acc0); acc1 = warpSum(acc1); acc2 = warpSum(acc2);
            acc3 = warpSum(acc3); acc4 = warpSum(acc4); acc5 = warpSum(acc5);
            if (lane == 0) {
                proj_s[lbase + 0] = acc0 + b_enc[lbase + 0];
                proj_s[lbase + 1] = acc1 + b_enc[lbase + 1];
                proj_s[lbase + 2] = acc2 + b_enc[lbase + 2];
                proj_s[lbase + 3] = acc3 + b_enc[lbase + 3];
                proj_s[lbase + 4] = acc4 + b_enc[lbase + 4];
                proj_s[lbase + 5] = acc5 + b_enc[lbase + 5];
            }
        }
        __syncthreads();

        // ---- Golay enc -> lattice round -> rescale -> Golay dec -> threshold ----
        if (w == 0) {
            float S_odd  = proj_s[13] + proj_s[15] + proj_s[17] + proj_s[19] + proj_s[21];
            float S_even = proj_s[12] + proj_s[14] + proj_s[16] + proj_s[18] + proj_s[20] + proj_s[22];
            float p23    = proj_s[23];

            float lr = 0.0f;
            if (lane < 12) {
                float ge = proj_s[lane] + ((lane & 1) ? (S_even + p23) : S_odd);
                lr = rintf(ge / eccv) * eccv;   // IEEE div: rintf boundary fidelity
            }
            float e_out = sqrtf(warpSum(lr * lr));
            float s1 = e_in / (e_out + 1e-8f);
            float lv = (lr * s1) * epv;
            float so2 = warpSum(lv * lv);
            if (lane == 0) ein2_s = sqrtf(so2);

            float L_even = warpSum((lane < 12 && !(lane & 1)) ? lv : 0.0f);
            float L_odd  = warpSum((lane < 12 &&  (lane & 1)) ? lv : 0.0f);
            if (lane < 12) latt_s[lane] = lv;
            __syncwarp();
            if (lane < 24) {
                float vv;
                if (lane < 12)      vv = latt_s[lane];
                else if (lane < 23) vv = (((lane - 12) & 1) == 0) ? L_odd : L_even;
                else                vv = L_odd;
                corr_s[lane] = (fabsf(vv) > eccv) ? vv : 0.0f;
            }
        }
        __syncthreads();

        // ---- res = corrected @ W_dec + b_dec (smem float4, conflict-free) ----
        float r0 = bd4.x, r1 = bd4.y, r2 = bd4.z, r3 = bd4.w;
#pragma unroll
        for (int l = 0; l < 24; l++) {
            float cl = corr_s[l];
            float4 wv = ((const float4*)(wdec_s + l * DD))[tid];
            r0 += cl * wv.x;  r1 += cl * wv.y;
            r2 += cl * wv.z;  r3 += cl * wv.w;
        }
        float ss2 = r0*r0 + r1*r1 + r2*r2 + r3*r3;
        float ss2tot = blockSum(ss2, red);
        float sc = ein2_s / (sqrtf(ss2tot) + 1e-8f);
        fpre[it] = sc * epv;
        rr[it] = make_float4(r0, r1, r2, r3);
        part[it] = fpre[it] * fpre[it] * ss2tot;
        __syncthreads();   // protect proj_s/corr_s/ein2_s before next iteration
    }

    // ---- grid barrier: publish Sigma res^2 (4 tokens), last block -> g_fac ----
    if (tid == 0) {
#pragma unroll
        for (int it = 0; it < TPB; it++) g_partial[bid * TPB + it] = part[it];
        __threadfence();
        unsigned int old = atomicAdd(&g_cnt, 1u);
        done_s = (old == NBLK - 1) ? 1 : 0;
    }
    __syncthreads();
    if (done_s) {
        float v = 0.0f;
#pragma unroll
        for (int i = 0; i < NTOK / NTHR; i++) v += g_partial[tid + i * NTHR];
        float tot = blockSum(v, red);
        if (tid == 0) {
            // fd cancels: out = res * frac_norm * ||res||
            *(volatile float*)&g_fac = frac_norm[0] * sqrtf(tot);
            __threadfence();
            atomicExch(&g_flag, 1u);
        }
    }
    if (tid == 0) {
        while (*(volatile unsigned int*)&g_flag == 0u) __nanosleep(64);
        fac_s = *(volatile float*)&g_fac;   // volatile: bypass (incoherent) L1
    }
    __syncthreads();
    const float facg = fac_s;

    // ---- final writes: 4 tokens, fully scaled, single pass ----
#pragma unroll
    for (int it = 0; it < TPB; it++) {
        const int tg = bid * TPB + it;
        const float fac = facg * fpre[it];
        float4 o4;
        o4.x = rr[it].x * fac;  o4.y = rr[it].y * fac;
        o4.z = rr[it].z * fac;  o4.w = rr[it].w * fac;
        ((float4*)out)[tg * (DD / 4) + tid] = o4;
    }

    // ---- self-reset for graph replay (after all blocks passed the spin) ----
    if (tid == 0) {
        unsigned int old2 = atomicAdd(&g_cnt2, 1u);
        if (old2 == NBLK - 1) {
            g_flag = 0u;
            g_cnt  = 0u;
            g_cnt2 = 0u;
        }
    }
}

extern "C" void kernel_launch(void* const* d_in, const int* in_sizes, int n_in,
                              void* d_out, int out_size)
{
    const int*   token_ids  = (const int*)  d_in[0];
    const float* resonances = (const float*)d_in[1];
    const float* emb_scales = (const float*)d_in[2];
    const float* emb_shifts = (const float*)d_in[3];
    const float* emb_norm   = (const float*)d_in[4];
    // d_in[5] scale_weights, d_in[6] fractal_bias: dead (fd cancels in fd*||res||/|fd|)
    const float* frac_norm  = (const float*)d_in[7];
    const float* W_enc      = (const float*)d_in[8];
    const float* b_enc      = (const float*)d_in[9];
    const float* W_dec      = (const float*)d_in[10];
    const float* b_dec      = (const float*)d_in[11];
    const float* ecc        = (const float*)d_in[12];
    const float* ep         = (const float*)d_in[13];
    float* out = (float*)d_out;

    // >48KB dynamic smem needs the attribute; host-side, not captured, capture-safe.
    cudaFuncSetAttribute(fused_kernel,
                         cudaFuncAttributeMaxDynamicSharedMemorySize, SMEM_DYN_BYTES);

    fused_kernel<<<NBLK, NTHR, SMEM_DYN_BYTES>>>(
        token_ids, resonances, emb_scales, emb_shifts, emb_norm, frac_norm,
        W_enc, b_enc, W_dec, b_dec, ecc, ep, out);
}

// round 13
// speedup vs baseline: 1.3440x; 1.3440x over previous
#include <cuda_runtime.h>

#define DD       512
#define TSEQ     512
#define NTOK     1024         // B*T
#define NTHR     128          // threads per block (4 warps)
#define TPB      2            // tokens per block
#define NBLK     (NTOK/TPB)   // 512 blocks; 4/SM by smem -> 592 slots, one wave
#define WE_STR   26           // padded W_enc row stride (even -> aligned LDS.64, 2-way max)

#define SMEM_WE_FLOATS  (DD * WE_STR)            // 13312 floats
#define SMEM_DYN_BYTES  (SMEM_WE_FLOATS * 4)     // 53248 bytes

__device__ float        g_partial[NTOK];
__device__ float        g_fac;
__device__ unsigned int g_cnt;    // arrival counter (self-resetting)
__device__ unsigned int g_cnt2;   // departure counter (self-resetting)
__device__ unsigned int g_flag;   // release flag     (self-resetting)

__device__ __forceinline__ float warpSum(float v) {
#pragma unroll
    for (int o = 16; o > 0; o >>= 1) v += __shfl_xor_sync(0xffffffffu, v, o);
    return v;  // butterfly: same value in all lanes, deterministic
}

// Deterministic block-wide sum (4 warps), broadcast to all threads.
__device__ __forceinline__ float blockSum(float v, float* red) {
    __syncthreads();                       // protect red[] reuse
    int lane = threadIdx.x & 31, w = threadIdx.x >> 5;
    v = warpSum(v);
    if (lane == 0) red[w] = v;
    __syncthreads();
    return red[0] + red[1] + red[2] + red[3];   // fixed order, all threads
}

__global__ __launch_bounds__(NTHR, 4) void fused_kernel(
    const int*   __restrict__ token_ids,
    const float* __restrict__ resonances,
    const float* __restrict__ emb_scales,
    const float* __restrict__ emb_shifts,
    const float* __restrict__ emb_norm,
    const float* __restrict__ frac_norm,
    const float* __restrict__ W_enc,   // [D,24]
    const float* __restrict__ b_enc,   // [24]
    const float* __restrict__ W_dec,   // [24,D]
    const float* __restrict__ b_dec,   // [D]
    const float* __restrict__ ecc_p,
    const float* __restrict__ ep_p,
    float*       __restrict__ out)     // [B,T,D]
{
    extern __shared__ float wenc_s[];             // [512][26] padded

    __shared__ float red[4];
    __shared__ float e0s[DD];
    __shared__ float proj_s[24];
    __shared__ float latt_s[12];
    __shared__ float corr_s[24];
    __shared__ float ein2_s;
    __shared__ float fac_s;
    __shared__ int   done_s;

    const int tid  = threadIdx.x;
    const int lane = tid & 31;
    const int w    = tid >> 5;
    const int bid  = blockIdx.x;

    // ---- stage W_enc: coalesced float4 LDG -> stride-26 smem repack ----
#pragma unroll
    for (int i4 = tid; i4 < (24 * DD) / 4; i4 += NTHR) {
        float4 v = ((const float4*)W_enc)[i4];
        int e = i4 * 4;
        float vv[4] = {v.x, v.y, v.z, v.w};
#pragma unroll
        for (int k = 0; k < 4; k++) {
            int ee = e + k;
            wenc_s[(ee / 24) * WE_STR + (ee % 24)] = vv[k];
        }
    }

    // ---- per-block invariants (shared by both tokens) ----
    const float4 rs4 = ((const float4*)resonances)[tid];
    const float4 sc4 = ((const float4*)emb_scales)[tid];
    const float4 sh4 = ((const float4*)emb_shifts)[tid];
    const float4 bd4 = ((const float4*)b_dec)[tid];
    const float rsv[4] = {rs4.x, rs4.y, rs4.z, rs4.w};
    const float scv[4] = {sc4.x, sc4.y, sc4.z, sc4.w};
    const float shv[4] = {sh4.x, sh4.y, sh4.z, sh4.w};
    const float embn = emb_norm[0];
    const float eccv = ecc_p[0];
    const float epv  = ep_p[0];
    __syncthreads();   // W_enc staged

    float4 rr[TPB];
    float  fpre[TPB];
    float  part[TPB];

#pragma unroll
    for (int it = 0; it < TPB; it++) {
        const int tg = bid * TPB + it;
        const int t  = tg & (TSEQ - 1);
        const float tv   = (float)(token_ids[tg] % 1000000) / 1000000.0f;
        const float base = tv + (float)t;

        // ---- embedding: comp = cos*(1+sin)+sin^2, scale/shift; d = 4*tid+i ----
        float e0[4];
        float ss = 0.0f;
#pragma unroll
        for (int i = 0; i < 4; i++) {
            float s, c;
            sincosf(rsv[i] * base, &s, &c);
            float v = (c * (1.0f + s) + s * s) * scv[i] + shv[i];
            e0[i] = v;
            ss += v * v;
        }
        float tn = sqrtf(blockSum(ss, red));
        // After normalize, ||emb|| == embn up to ~1e-7 rounding; skip 2nd reduce.
        float e_in = (tn > 0.0f) ? embn : 0.0f;

        float4 ev4;
#pragma unroll
        for (int i = 0; i < 4; i++) {
            float v = (tn > 0.0f) ? (e0[i] * embn) / tn : e0[i];
            ((float*)&ev4)[i] = v;
        }
        ((float4*)e0s)[tid] = ev4;
        __syncthreads();

        // ---- proj = emb @ W_enc + b_enc: warp w owns outputs [6w,6w+6) ----
        // Same read pattern & FMA order as the 18.9us kernel, but from smem.
        {
            const int lbase = w * 6;
            float acc0=0.f, acc1=0.f, acc2=0.f, acc3=0.f, acc4=0.f, acc5=0.f;
#pragma unroll
            for (int j = 0; j < 16; j++) {
                int d = lane + 32 * j;
                float ev = e0s[d];
                const float2* w2 = (const float2*)(wenc_s + d * WE_STR + lbase);
                float2 a = w2[0], b = w2[1], c = w2[2];
                acc0 += ev * a.x;  acc1 += ev * a.y;
                acc2 += ev * b.x;  acc3 += ev * b.y;
                acc4 += ev * c.x;  acc5 += ev * c.y;
            }
            acc0 = warpSum(acc0); acc1 = warpSum(acc1); acc2 = warpSum(acc2);
            acc3 = warpSum(acc3); acc4 = warpSum(acc4); acc5 = warpSum(acc5);
            if (lane == 0) {
                proj_s[lbase + 0] = acc0 + b_enc[lbase + 0];
                proj_s[lbase + 1] = acc1 + b_enc[lbase + 1];
                proj_s[lbase + 2] = acc2 + b_enc[lbase + 2];
                proj_s[lbase + 3] = acc3 + b_enc[lbase + 3];
                proj_s[lbase + 4] = acc4 + b_enc[lbase + 4];
                proj_s[lbase + 5] = acc5 + b_enc[lbase + 5];
            }
        }
        __syncthreads();

        // ---- Golay enc -> lattice round -> rescale -> Golay dec -> threshold ----
        if (w == 0) {
            float S_odd  = proj_s[13] + proj_s[15] + proj_s[17] + proj_s[19] + proj_s[21];
            float S_even = proj_s[12] + proj_s[14] + proj_s[16] + proj_s[18] + proj_s[20] + proj_s[22];
            float p23    = proj_s[23];

            float lr = 0.0f;
            if (lane < 12) {
                float ge = proj_s[lane] + ((lane & 1) ? (S_even + p23) : S_odd);
                lr = rintf(ge / eccv) * eccv;   // IEEE div: rintf boundary fidelity
            }
            float e_out = sqrtf(warpSum(lr * lr));
            float s1 = e_in / (e_out + 1e-8f);
            float lv = (lr * s1) * epv;
            float so2 = warpSum(lv * lv);
            if (lane == 0) ein2_s = sqrtf(so2);

            float L_even = warpSum((lane < 12 && !(lane & 1)) ? lv : 0.0f);
            float L_odd  = warpSum((lane < 12 &&  (lane & 1)) ? lv : 0.0f);
            if (lane < 12) latt_s[lane] = lv;
            __syncwarp();
            if (lane < 24) {
                float vv;
                if (lane < 12)      vv = latt_s[lane];
                else if (lane < 23) vv = (((lane - 12) & 1) == 0) ? L_odd : L_even;
                else                vv = L_odd;
                corr_s[lane] = (fabsf(vv) > eccv) ? vv : 0.0f;
            }
        }
        __syncthreads();

        // ---- res = corrected @ W_dec + b_dec (global float4, coalesced) ----
        float r0 = bd4.x, r1 = bd4.y, r2 = bd4.z, r3 = bd4.w;
#pragma unroll
        for (int l = 0; l < 24; l++) {
            float cl = corr_s[l];
            float4 wv = ((const float4*)(W_dec + l * DD))[tid];
            r0 += cl * wv.x;  r1 += cl * wv.y;
            r2 += cl * wv.z;  r3 += cl * wv.w;
        }
        float ss2 = r0*r0 + r1*r1 + r2*r2 + r3*r3;
        float ss2tot = blockSum(ss2, red);
        float sc = ein2_s / (sqrtf(ss2tot) + 1e-8f);
        fpre[it] = sc * epv;
        rr[it] = make_float4(r0, r1, r2, r3);
        part[it] = fpre[it] * fpre[it] * ss2tot;
        __syncthreads();   // protect proj_s/corr_s/ein2_s before next token
    }

    // ---- grid barrier: publish Sigma res^2 (2 tokens), last block -> g_fac ----
    if (tid == 0) {
#pragma unroll
        for (int it = 0; it < TPB; it++) g_partial[bid * TPB + it] = part[it];
        __threadfence();
        unsigned int old = atomicAdd(&g_cnt, 1u);
        done_s = (old == NBLK - 1) ? 1 : 0;
    }
    __syncthreads();
    if (done_s) {
        float v = 0.0f;
#pragma unroll
        for (int i = 0; i < NTOK / NTHR; i++) v += g_partial[tid + i * NTHR];
        float tot = blockSum(v, red);
        if (tid == 0) {
            // fd cancels: out = res * frac_norm * ||res||
            *(volatile float*)&g_fac = frac_norm[0] * sqrtf(tot);
            __threadfence();
            atomicExch(&g_flag, 1u);
        }
    }
    if (tid == 0) {
        while (*(volatile unsigned int*)&g_flag == 0u) __nanosleep(64);
        fac_s = *(volatile float*)&g_fac;   // volatile: bypass (incoherent) L1
    }
    __syncthreads();
    const float facg = fac_s;

    // ---- final writes: 2 tokens, fully scaled, single pass ----
#pragma unroll
    for (int it = 0; it < TPB; it++) {
        const int tg = bid * TPB + it;
        const float fac = facg * fpre[it];
        float4 o4;
        o4.x = rr[it].x * fac;  o4.y = rr[it].y * fac;
        o4.z = rr[it].z * fac;  o4.w = rr[it].w * fac;
        ((float4*)out)[tg * (DD / 4) + tid] = o4;
    }

    // ---- self-reset for graph replay (after all blocks passed the spin) ----
    if (tid == 0) {
        unsigned int old2 = atomicAdd(&g_cnt2, 1u);
        if (old2 == NBLK - 1) {
            g_flag = 0u;
            g_cnt  = 0u;
            g_cnt2 = 0u;
        }
    }
}

extern "C" void kernel_launch(void* const* d_in, const int* in_sizes, int n_in,
                              void* d_out, int out_size)
{
    const int*   token_ids  = (const int*)  d_in[0];
    const float* resonances = (const float*)d_in[1];
    const float* emb_scales = (const float*)d_in[2];
    const float* emb_shifts = (const float*)d_in[3];
    const float* emb_norm   = (const float*)d_in[4];
    // d_in[5] scale_weights, d_in[6] fractal_bias: dead (fd cancels in fd*||res||/|fd|)
    const float* frac_norm  = (const float*)d_in[7];
    const float* W_enc      = (const float*)d_in[8];
    const float* b_enc      = (const float*)d_in[9];
    const float* W_dec      = (const float*)d_in[10];
    const float* b_dec      = (const float*)d_in[11];
    const float* ecc        = (const float*)d_in[12];
    const float* ep         = (const float*)d_in[13];
    float* out = (float*)d_out;

    // >48KB dynamic smem needs the attribute; host API, capture-safe.
    cudaFuncSetAttribute(fused_kernel,
                         cudaFuncAttributeMaxDynamicSharedMemorySize, SMEM_DYN_BYTES);

    fused_kernel<<<NBLK, NTHR, SMEM_DYN_BYTES>>>(
        token_ids, resonances, emb_scales, emb_shifts, emb_norm, frac_norm,
        W_enc, b_enc, W_dec, b_dec, ecc, ep, out);
}

// round 14
// speedup vs baseline: 1.6430x; 1.2224x over previous
#include <cuda_runtime.h>

#define DD      512
#define TSEQ    512
#define NTOK    1024          // B*T
#define NTHR    128           // threads per token block (4 warps)

__device__ float        g_wencT[24 * DD];   // W_enc transposed: [24][512]
__device__ float        g_partial[NTOK];
__device__ float        g_fac;
__device__ unsigned int g_cnt;    // arrival counter (self-resetting)
__device__ unsigned int g_cnt2;   // departure counter (self-resetting)
__device__ unsigned int g_flag;   // release flag     (self-resetting)

__device__ __forceinline__ float warpSum(float v) {
#pragma unroll
    for (int o = 16; o > 0; o >>= 1) v += __shfl_xor_sync(0xffffffffu, v, o);
    return v;  // butterfly: same value in all lanes, deterministic
}

// Deterministic block-wide sum (4 warps), broadcast to all threads.
__device__ __forceinline__ float blockSum(float v, float* red) {
    __syncthreads();                       // protect red[] reuse
    int lane = threadIdx.x & 31, w = threadIdx.x >> 5;
    v = warpSum(v);
    if (lane == 0) red[w] = v;
    __syncthreads();
    return red[0] + red[1] + red[2] + red[3];   // fixed order, all threads
}

// Tiny pre-pass: W_enc [512,24] -> W_encT [24,512]; coalesced writes.
// Recomputed every launch (deterministic, no guards).
__global__ __launch_bounds__(256) void transpose_kernel(const float* __restrict__ W_enc)
{
    int i = blockIdx.x * 256 + threadIdx.x;   // i = l*512 + d
    int l = i >> 9;
    int d = i & 511;
    g_wencT[i] = W_enc[d * 24 + l];
}

__global__ __launch_bounds__(NTHR, 8) void fused_kernel(
    const int*   __restrict__ token_ids,
    const float* __restrict__ resonances,
    const float* __restrict__ emb_scales,
    const float* __restrict__ emb_shifts,
    const float* __restrict__ emb_norm,
    const float* __restrict__ frac_norm,
    const float* __restrict__ b_enc,   // [24]
    const float* __restrict__ W_dec,   // [24,D]
    const float* __restrict__ b_dec,   // [D]
    const float* __restrict__ ecc_p,
    const float* __restrict__ ep_p,
    float*       __restrict__ out)     // [B,T,D]
{
    __shared__ float red[4];
    __shared__ float e0s[DD];
    __shared__ float proj_s[24];
    __shared__ float latt_s[12];
    __shared__ float corr_s[24];
    __shared__ float ein2_s;
    __shared__ float fac_s;
    __shared__ int   done_s;

    const int tid  = threadIdx.x;
    const int lane = tid & 31;
    const int w    = tid >> 5;
    const int tg   = blockIdx.x;
    const int t    = tg & (TSEQ - 1);

    const float tv   = (float)(token_ids[tg] % 1000000) / 1000000.0f;
    const float base = tv + (float)t;
    const float embn = emb_norm[0];
    const float eccv = ecc_p[0];
    const float epv  = ep_p[0];

    // ---- embedding: comp = cos*(1+sin)+sin^2, scale/shift; d = 4*tid + i ----
    const float4 rs4 = ((const float4*)resonances)[tid];
    const float4 sc4 = ((const float4*)emb_scales)[tid];
    const float4 sh4 = ((const float4*)emb_shifts)[tid];
    const float rsv[4] = {rs4.x, rs4.y, rs4.z, rs4.w};
    const float scv[4] = {sc4.x, sc4.y, sc4.z, sc4.w};
    const float shv[4] = {sh4.x, sh4.y, sh4.z, sh4.w};

    float e0[4];
    float ss = 0.0f;
#pragma unroll
    for (int i = 0; i < 4; i++) {
        float s, c;
        sincosf(rsv[i] * base, &s, &c);
        float v = (c * (1.0f + s) + s * s) * scv[i] + shv[i];
        e0[i] = v;
        ss += v * v;
    }
    float tn = sqrtf(blockSum(ss, red));
    // After normalize, ||emb|| == embn up to ~1e-7 rounding; skip second reduce.
    float e_in = (tn > 0.0f) ? embn : 0.0f;

    float4 ev4w;
#pragma unroll
    for (int i = 0; i < 4; i++) {
        float v = (tn > 0.0f) ? (e0[i] * embn) / tn : e0[i];
        ((float*)&ev4w)[i] = v;
    }
    ((float4*)e0s)[tid] = ev4w;
    __syncthreads();

    // ---- proj = emb @ W_enc + b_enc via W_encT: fully coalesced float4 ----
    // Warp w owns outputs [6w, 6w+6).
    {
        const int lbase = w * 6;
        float acc0=0.f, acc1=0.f, acc2=0.f, acc3=0.f, acc4=0.f, acc5=0.f;
#pragma unroll
        for (int jj = 0; jj < 4; jj++) {
            const int idx = lane + 32 * jj;           // float4 index into 512 floats
            float4 ev = ((const float4*)e0s)[idx];
            float4 w0 = ((const float4*)(g_wencT + (lbase + 0) * DD))[idx];
            float4 w1 = ((const float4*)(g_wencT + (lbase + 1) * DD))[idx];
            float4 w2 = ((const float4*)(g_wencT + (lbase + 2) * DD))[idx];
            float4 w3 = ((const float4*)(g_wencT + (lbase + 3) * DD))[idx];
            float4 w4 = ((const float4*)(g_wencT + (lbase + 4) * DD))[idx];
            float4 w5 = ((const float4*)(g_wencT + (lbase + 5) * DD))[idx];
            acc0 += ev.x*w0.x + ev.y*w0.y + ev.z*w0.z + ev.w*w0.w;
            acc1 += ev.x*w1.x + ev.y*w1.y + ev.z*w1.z + ev.w*w1.w;
            acc2 += ev.x*w2.x + ev.y*w2.y + ev.z*w2.z + ev.w*w2.w;
            acc3 += ev.x*w3.x + ev.y*w3.y + ev.z*w3.z + ev.w*w3.w;
            acc4 += ev.x*w4.x + ev.y*w4.y + ev.z*w4.z + ev.w*w4.w;
            acc5 += ev.x*w5.x + ev.y*w5.y + ev.z*w5.z + ev.w*w5.w;
        }
        acc0 = warpSum(acc0); acc1 = warpSum(acc1); acc2 = warpSum(acc2);
        acc3 = warpSum(acc3); acc4 = warpSum(acc4); acc5 = warpSum(acc5);
        if (lane == 0) {
            proj_s[lbase + 0] = acc0 + b_enc[lbase + 0];
            proj_s[lbase + 1] = acc1 + b_enc[lbase + 1];
            proj_s[lbase + 2] = acc2 + b_enc[lbase + 2];
            proj_s[lbase + 3] = acc3 + b_enc[lbase + 3];
            proj_s[lbase + 4] = acc4 + b_enc[lbase + 4];
            proj_s[lbase + 5] = acc5 + b_enc[lbase + 5];
        }
    }
    __syncthreads();

    // ---- Golay enc -> lattice round -> rescale -> Golay dec -> threshold ----
    if (w == 0) {
        float S_odd  = proj_s[13] + proj_s[15] + proj_s[17] + proj_s[19] + proj_s[21];
        float S_even = proj_s[12] + proj_s[14] + proj_s[16] + proj_s[18] + proj_s[20] + proj_s[22];
        float p23    = proj_s[23];

        float lr = 0.0f;
        if (lane < 12) {
            float ge = proj_s[lane] + ((lane & 1) ? (S_even + p23) : S_odd);
            lr = rintf(ge / eccv) * eccv;       // IEEE div: rintf boundary fidelity
        }
        float e_out = sqrtf(warpSum(lr * lr));
        float s1 = e_in / (e_out + 1e-8f);
        float lv = (lr * s1) * epv;
        float so2 = warpSum(lv * lv);
        if (lane == 0) ein2_s = sqrtf(so2);

        float L_even = warpSum((lane < 12 && !(lane & 1)) ? lv : 0.0f);
        float L_odd  = warpSum((lane < 12 &&  (lane & 1)) ? lv : 0.0f);
        if (lane < 12) latt_s[lane] = lv;
        __syncwarp();
        if (lane < 24) {
            float vv;
            if (lane < 12)      vv = latt_s[lane];
            else if (lane < 23) vv = (((lane - 12) & 1) == 0) ? L_odd : L_even;
            else                vv = L_odd;
            corr_s[lane] = (fabsf(vv) > eccv) ? vv : 0.0f;
        }
    }
    __syncthreads();

    // ---- res = corrected @ W_dec + b_dec (global float4, coalesced) ----
    const float4 bd4 = ((const float4*)b_dec)[tid];
    float r0 = bd4.x, r1 = bd4.y, r2 = bd4.z, r3 = bd4.w;
#pragma unroll
    for (int l = 0; l < 24; l++) {
        float cl = corr_s[l];
        float4 wv = ((const float4*)(W_dec + l * DD))[tid];
        r0 += cl * wv.x;  r1 += cl * wv.y;
        r2 += cl * wv.z;  r3 += cl * wv.w;
    }
    float ss2 = r0*r0 + r1*r1 + r2*r2 + r3*r3;
    float ss2tot = blockSum(ss2, red);
    float sc = ein2_s / (sqrtf(ss2tot) + 1e-8f);
    float fpre = sc * epv;                 // per-token rescale (res stays in regs)

    // ---- grid barrier: publish Sigma res^2, last block reduces -> g_fac ----
    if (tid == 0) {
        g_partial[tg] = fpre * fpre * ss2tot;
        __threadfence();
        unsigned int old = atomicAdd(&g_cnt, 1u);
        done_s = (old == NTOK - 1) ? 1 : 0;
    }
    __syncthreads();
    if (done_s) {
        float v = 0.0f;
#pragma unroll
        for (int i = 0; i < NTOK / NTHR; i++) v += g_partial[tid + i * NTHR];
        float tot = blockSum(v, red);
        if (tid == 0) {
            // fd cancels: out = res * frac_norm * ||res||
            *(volatile float*)&g_fac = frac_norm[0] * sqrtf(tot);
            __threadfence();
            atomicExch(&g_flag, 1u);
        }
    }
    if (tid == 0) {
        while (*(volatile unsigned int*)&g_flag == 0u) __nanosleep(64);
        fac_s = *(volatile float*)&g_fac;   // volatile: bypass (incoherent) L1
    }
    __syncthreads();
    const float fac = fac_s * fpre;

    // ---- single output write, fully scaled ----
    float4 o4;
    o4.x = r0 * fac;  o4.y = r1 * fac;
    o4.z = r2 * fac;  o4.w = r3 * fac;
    ((float4*)out)[tg * (DD / 4) + tid] = o4;

    // ---- self-reset for graph replay (after all blocks passed the spin) ----
    if (tid == 0) {
        unsigned int old2 = atomicAdd(&g_cnt2, 1u);
        if (old2 == NTOK - 1) {
            g_flag = 0u;
            g_cnt  = 0u;
            g_cnt2 = 0u;
        }
    }
}

extern "C" void kernel_launch(void* const* d_in, const int* in_sizes, int n_in,
                              void* d_out, int out_size)
{
    const int*   token_ids  = (const int*)  d_in[0];
    const float* resonances = (const float*)d_in[1];
    const float* emb_scales = (const float*)d_in[2];
    const float* emb_shifts = (const float*)d_in[3];
    const float* emb_norm   = (const float*)d_in[4];
    // d_in[5] scale_weights, d_in[6] fractal_bias: dead (fd cancels in fd*||res||/|fd|)
    const float* frac_norm  = (const float*)d_in[7];
    const float* W_enc      = (const float*)d_in[8];
    const float* b_enc      = (const float*)d_in[9];
    const float* W_dec      = (const float*)d_in[10];
    const float* b_dec      = (const float*)d_in[11];
    const float* ecc        = (const float*)d_in[12];
    const float* ep         = (const float*)d_in[13];
    float* out = (float*)d_out;

    transpose_kernel<<<(24 * DD) / 256, 256>>>(W_enc);
    fused_kernel<<<NTOK, NTHR>>>(token_ids, resonances, emb_scales, emb_shifts,
                                 emb_norm, frac_norm, b_enc, W_dec, b_dec,
                                 ecc, ep, out);
}